// round 5
// baseline (speedup 1.0000x reference)
#include <cuda_runtime.h>
#include <math.h>

#define BB 2
#define SS 1024
#define TT 1024
#define DS 128
#define DT 64
#define H 64
#define LN_EPS 1e-5f

#define TILE_T 8
#define CH 32
#define USTRIDE 68   // floats; 272B row stride, 16B-aligned, conflict-free 16B reads
#define TTG 8        // t-rows per transfer block

typedef unsigned long long ull;

__device__ __forceinline__ ull fma2(ull a, ull b, ull c) {
    ull d; asm("fma.rn.f32x2 %0,%1,%2,%3;" : "=l"(d) : "l"(a), "l"(b), "l"(c)); return d;
}
__device__ __forceinline__ ull add2(ull a, ull b) {
    ull d; asm("add.rn.f32x2 %0,%1,%2;" : "=l"(d) : "l"(a), "l"(b)); return d;
}
__device__ __forceinline__ ull pack2(float lo, float hi) {
    ull d; asm("mov.b64 %0,{%1,%2};" : "=l"(d) : "f"(lo), "f"(hi)); return d;
}
__device__ __forceinline__ float2 unpack2(ull v) {
    float2 r; asm("mov.b64 {%0,%1},%2;" : "=f"(r.x), "=f"(r.y) : "l"(v)); return r;
}
__device__ __forceinline__ void cp16(void* smem_dst, const void* gsrc) {
    unsigned sa = (unsigned)__cvta_generic_to_shared(smem_dst);
    asm volatile("cp.async.cg.shared.global [%0], [%1], 16;" :: "r"(sa), "l"(gsrc));
}

// ---------------- scratch ----------------
__device__ float g_s_ad[BB * SS * H];
__device__ float g_u[BB * SS * H];
__device__ float g_t_ad[BB * TT * H];
__device__ float g_a[BB * TT * H];
__device__ float g_sum_u[BB * SS];
__device__ float g_su2[BB * SS];
__device__ float g_sum_a[BB * TT];
__device__ float g_sa2[BB * TT];
__device__ float g_gate[BB * TT];
__device__ float g_sumexp[BB * TT];

// ---------------- adapter ----------------
template <int DIN, bool IS_TARGET>
__global__ __launch_bounds__(256)
void adapter_kernel(const float* __restrict__ X,
                    const float* __restrict__ W1, const float* __restrict__ b1,
                    const float* __restrict__ g,  const float* __restrict__ beta,
                    const float* __restrict__ W2, const float* __restrict__ b2,
                    const float* __restrict__ cWpart, const float* __restrict__ cb)
{
    __shared__ float sh_x[4][DIN];
    __shared__ float sh_r[4][H];
    __shared__ float sh_ad[4][H];
    __shared__ float sh_red[4][4];

    const int gid = threadIdx.x >> 6;
    const int j = threadIdx.x & 63;
    const int wid = j >> 5;
    const int row = blockIdx.x * 4 + gid;

    const float4* xrow4 = (const float4*)(X + (size_t)row * DIN);
    if (j < DIN / 4) ((float4*)sh_x[gid])[j] = xrow4[j];
    __syncthreads();

    const float* sx = sh_x[gid];
    float h0 = 0.f, h1 = 0.f, h2 = 0.f, h3 = 0.f;
#pragma unroll
    for (int k = 0; k < DIN; k += 4) {
        h0 = fmaf(sx[k],     W1[(k)     * H + j], h0);
        h1 = fmaf(sx[k + 1], W1[(k + 1) * H + j], h1);
        h2 = fmaf(sx[k + 2], W1[(k + 2) * H + j], h2);
        h3 = fmaf(sx[k + 3], W1[(k + 3) * H + j], h3);
    }
    float h = ((h0 + h1) + (h2 + h3)) + b1[j];

    float s1 = h, s2 = h * h;
#pragma unroll
    for (int o = 16; o; o >>= 1) {
        s1 += __shfl_xor_sync(~0u, s1, o);
        s2 += __shfl_xor_sync(~0u, s2, o);
    }
    if ((j & 31) == 0) { sh_red[gid][wid] = s1; sh_red[gid][2 + wid] = s2; }
    __syncthreads();
    const float m   = (sh_red[gid][0] + sh_red[gid][1]) * (1.f / H);
    const float e2  = (sh_red[gid][2] + sh_red[gid][3]) * (1.f / H);
    const float inv = rsqrtf(e2 - m * m + LN_EPS);
    float r = (h - m) * inv * g[j] + beta[j];
    r = fmaxf(r, 0.f);
    __syncthreads();
    sh_r[gid][j] = r;
    __syncthreads();

    const float* sr = sh_r[gid];
    float a0 = 0.f, a1 = 0.f, a2v = 0.f, a3 = 0.f;
#pragma unroll
    for (int k = 0; k < H; k += 4) {
        a0  = fmaf(sr[k],     W2[(k)     * H + j], a0);
        a1  = fmaf(sr[k + 1], W2[(k + 1) * H + j], a1);
        a2v = fmaf(sr[k + 2], W2[(k + 2) * H + j], a2v);
        a3  = fmaf(sr[k + 3], W2[(k + 3) * H + j], a3);
    }
    float ad = ((a0 + a1) + (a2v + a3)) + b2[j];

    if (IS_TARGET) {
        g_t_ad[(size_t)row * H + j] = ad;
        float s = ad;
#pragma unroll
        for (int o = 16; o; o >>= 1) s += __shfl_xor_sync(~0u, s, o);
        if ((j & 31) == 0) sh_red[gid][wid] = s;
    } else {
        g_s_ad[(size_t)row * H + j] = ad;
    }
    sh_ad[gid][j] = ad;
    __syncthreads();

    if (IS_TARGET && j == 0) {
        float mt = (sh_red[gid][0] + sh_red[gid][1]) * (1.f / H);
        g_gate[row] = 1.f / (1.f + __expf(-mt));
    }

    const float* sa = sh_ad[gid];
    float p0 = IS_TARGET ? cb[j] : 0.f, p1k = 0.f, p2k = 0.f, p3k = 0.f;
#pragma unroll
    for (int k = 0; k < H; k += 4) {
        p0  = fmaf(sa[k],     cWpart[(k)     * H + j], p0);
        p1k = fmaf(sa[k + 1], cWpart[(k + 1) * H + j], p1k);
        p2k = fmaf(sa[k + 2], cWpart[(k + 2) * H + j], p2k);
        p3k = fmaf(sa[k + 3], cWpart[(k + 3) * H + j], p3k);
    }
    float p = ((p0 + p1k) + (p2k + p3k));

    if (IS_TARGET) g_a[(size_t)row * H + j] = p;
    else           g_u[(size_t)row * H + j] = p;

    float q1 = p, q2 = p * p;
#pragma unroll
    for (int o = 16; o; o >>= 1) {
        q1 += __shfl_xor_sync(~0u, q1, o);
        q2 += __shfl_xor_sync(~0u, q2, o);
    }
    __syncthreads();
    if ((j & 31) == 0) { sh_red[gid][wid] = q1; sh_red[gid][2 + wid] = q2; }
    __syncthreads();
    if (j == 0) {
        if (IS_TARGET) { g_sum_a[row] = sh_red[gid][0] + sh_red[gid][1]; g_sa2[row] = sh_red[gid][2] + sh_red[gid][3]; }
        else           { g_sum_u[row] = sh_red[gid][0] + sh_red[gid][1]; g_su2[row] = sh_red[gid][2] + sh_red[gid][3]; }
    }
}

// ---------------- score kernel: u in regs, a + constants in smem, cp.async pipeline ----
__global__ __launch_bounds__(256, 2)
void score_kernel(const float* __restrict__ cg, const float* __restrict__ cbeta,
                  const float* __restrict__ simW, const float* __restrict__ simb,
                  float* __restrict__ out_scores)
{
    __shared__ __align__(16) float u_sh[2][CH * USTRIDE];
    __shared__ __align__(16) float a_sh[TILE_T][H];
    __shared__ __align__(16) ull k_sh[H / 4][8];   // [i]: cg01 cg23 cb01 cb23 w01 w23 - -

    const int tid = threadIdx.x;
    const int lane = tid & 31;
    const int w = tid >> 5;
    const int tglob = blockIdx.x * TILE_T + w;
    const int b = tglob >> 10;
    const int srow0 = b << 10;

    // constants tile (once per block): 16 threads fill 16 rows
    if (tid < H / 4) {
        const int i = tid;
        k_sh[i][0] = pack2(cg[4 * i],     cg[4 * i + 1]);
        k_sh[i][1] = pack2(cg[4 * i + 2], cg[4 * i + 3]);
        k_sh[i][2] = pack2(cbeta[4 * i],     cbeta[4 * i + 1]);
        k_sh[i][3] = pack2(cbeta[4 * i + 2], cbeta[4 * i + 3]);
        k_sh[i][4] = pack2(simW[4 * i],     simW[4 * i + 1]);
        k_sh[i][5] = pack2(simW[4 * i + 2], simW[4 * i + 3]);
    }

    // stage this warp's a row to shared (warp-uniform -> broadcast reads later)
    ((float2*)a_sh[w])[lane] = ((const float2*)(g_a + (size_t)tglob * H))[lane];

    const float suma = g_sum_a[tglob];
    const float sqa  = g_sa2[tglob];
    const float simb0 = simb[0];

    // prologue: stage chunk 0
    {
        const float4* src = (const float4*)(g_u + (size_t)srow0 * H);
#pragma unroll
        for (int rep = 0; rep < 2; rep++) {
            int f = tid + rep * 256;
            int r = f >> 4, q = f & 15;
            cp16(&u_sh[0][r * USTRIDE + q * 4], src + f);
        }
        asm volatile("cp.async.commit_group;");
    }

    float sumexp = 0.f;
    float* srow_out = out_scores + (size_t)tglob * SS;
    __syncthreads();   // a_sh + k_sh visible

    for (int c = 0; c < SS / CH; c++) {
        if (c < SS / CH - 1) {
            const float4* src = (const float4*)(g_u + (size_t)(srow0 + (c + 1) * CH) * H);
            float* dst = u_sh[(c + 1) & 1];
#pragma unroll
            for (int rep = 0; rep < 2; rep++) {
                int f = tid + rep * 256;
                int r = f >> 4, q = f & 15;
                cp16(&dst[r * USTRIDE + q * 4], src + f);
            }
            asm volatile("cp.async.commit_group;");
            asm volatile("cp.async.wait_group 1;");
        } else {
            asm volatile("cp.async.wait_group 0;");
        }
        __syncthreads();

        // load u row for this lane's s ONCE into registers
        const ulonglong2* up2 = (const ulonglong2*)&u_sh[c & 1][lane * USTRIDE];
        ull u2[H / 2];
#pragma unroll
        for (int i = 0; i < H / 4; i++) {
            ulonglong2 v = up2[i];
            u2[2 * i] = v.x; u2[2 * i + 1] = v.y;
        }

        const int sidx = srow0 + c * CH + lane;
        const float su  = g_sum_u[sidx];
        const float squ = g_su2[sidx];

        const ulonglong2* ap2 = (const ulonglong2*)a_sh[w];

        // pass 1: dot(a,u), a via broadcast LDS
        ull d0 = 0ull, d1 = 0ull, d2 = 0ull, d3 = 0ull;
#pragma unroll
        for (int i = 0; i < H / 4; i += 2) {
            ulonglong2 aa = ap2[i];
            ulonglong2 ab = ap2[i + 1];
            d0 = fma2(aa.x, u2[2 * i],     d0);
            d1 = fma2(aa.y, u2[2 * i + 1], d1);
            d2 = fma2(ab.x, u2[2 * i + 2], d2);
            d3 = fma2(ab.y, u2[2 * i + 3], d3);
        }
        float2 f0 = unpack2(d0), f1 = unpack2(d1), f2 = unpack2(d2), f3 = unpack2(d3);
        const float dot = ((f0.x + f0.y) + (f1.x + f1.y)) + ((f2.x + f2.y) + (f3.x + f3.y));

        const float m   = (suma + su) * (1.f / H);
        const float e2  = (sqa + 2.f * dot + squ) * (1.f / H);
        const float inv = rsqrtf(e2 - m * m + LN_EPS);
        const float nm  = -m * inv;
        const ull inv2 = pack2(inv, inv);
        const ull nm2  = pack2(nm, nm);

        // pass 2: fully packed; u regs, a broadcast LDS, constants broadcast LDS
        ull acca = 0ull, accb = 0ull;
#pragma unroll
        for (int i = 0; i < H / 4; i++) {
            ulonglong2 aa  = ap2[i];
            ulonglong2 kcg = *(const ulonglong2*)&k_sh[i][0];
            ulonglong2 kcb = *(const ulonglong2*)&k_sh[i][2];
            ulonglong2 kw  = *(const ulonglong2*)&k_sh[i][4];
            ull p0 = add2(aa.x, u2[2 * i]);
            ull p1 = add2(aa.y, u2[2 * i + 1]);
            ull z0 = fma2(p0, inv2, nm2);
            ull z1 = fma2(p1, inv2, nm2);
            ull y0 = fma2(z0, kcg.x, kcb.x);
            ull y1 = fma2(z1, kcg.y, kcb.y);
            float2 ya = unpack2(y0), yb = unpack2(y1);
            ya.x = fmaxf(ya.x, 0.f); ya.y = fmaxf(ya.y, 0.f);
            yb.x = fmaxf(yb.x, 0.f); yb.y = fmaxf(yb.y, 0.f);
            acca = fma2(pack2(ya.x, ya.y), kw.x, acca);
            accb = fma2(pack2(yb.x, yb.y), kw.y, accb);
        }
        float2 sa2 = unpack2(acca), sb2 = unpack2(accb);
        const float acc = (sa2.x + sa2.y) + (sb2.x + sb2.y);
        const float score = 1.f / (1.f + __expf(-(acc + simb0)));
        srow_out[c * CH + lane] = score;
        sumexp += __expf(score);

        __syncthreads();   // reads of this buffer done before re-stage
    }

#pragma unroll
    for (int o = 16; o; o >>= 1) sumexp += __shfl_xor_sync(~0u, sumexp, o);
    if (lane == 0) g_sumexp[tglob] = sumexp;
}

// ---------------- transfer: 512 threads / 16 warps, warp covers 64 s, TTG=8 t-rows ----
__global__ __launch_bounds__(512, 3)
void transfer_kernel(const float* __restrict__ scores, float* __restrict__ out_adapted)
{
    __shared__ __align__(16) ull e2_sh[16][32 * TTG];   // 32 KB duplicated-exp per warp
    __shared__ __align__(16) float red[16 * TTG * H];   // 32 KB per-warp partials

    const int tid = threadIdx.x;
    const int w = tid >> 5, lane = tid & 31;
    const int tbase = blockIdx.x * TTG;
    const int b = tbase >> 10;
    const int srow0 = b << 10;

    ull acc2[TTG];
#pragma unroll
    for (int t = 0; t < TTG; t++) acc2[t] = 0ull;

    for (int c = 0; c < 2; c++) {
        const int sloc0 = w * 64 + c * 32;

#pragma unroll
        for (int t = 0; t < TTG; t++) {
            float e = __expf(scores[(size_t)(tbase + t) * SS + sloc0 + lane]);
            e2_sh[w][lane * TTG + t] = pack2(e, e);
        }
        __syncwarp();

#pragma unroll 8
        for (int j = 0; j < 32; j += 4) {
            // batch 4 independent s_ad loads (MLP=4; lower reg pressure for occ=3)
            ull v[4];
#pragma unroll
            for (int k = 0; k < 4; k++)
                v[k] = *(const ull*)(g_s_ad + (size_t)(srow0 + sloc0 + j + k) * H + 2 * lane);
#pragma unroll
            for (int k = 0; k < 4; k++) {
                const ulonglong2* ep = (const ulonglong2*)&e2_sh[w][(j + k) * TTG];
                ulonglong2 e01 = ep[0], e23 = ep[1], e45 = ep[2], e67 = ep[3];
                acc2[0] = fma2(v[k], e01.x, acc2[0]);
                acc2[1] = fma2(v[k], e01.y, acc2[1]);
                acc2[2] = fma2(v[k], e23.x, acc2[2]);
                acc2[3] = fma2(v[k], e23.y, acc2[3]);
                acc2[4] = fma2(v[k], e45.x, acc2[4]);
                acc2[5] = fma2(v[k], e45.y, acc2[5]);
                acc2[6] = fma2(v[k], e67.x, acc2[6]);
                acc2[7] = fma2(v[k], e67.y, acc2[7]);
            }
        }
        __syncwarp();
    }

#pragma unroll
    for (int t = 0; t < TTG; t++)
        *(ull*)&red[(w * TTG + t) * H + 2 * lane] = acc2[t];
    __syncthreads();

    const int t = tid >> 6;
    const int hh = tid & 63;
    float s = 0.f;
#pragma unroll
    for (int ww = 0; ww < 16; ww++) s += red[(ww * TTG + t) * H + hh];

    const int tg = tbase + t;
    const float rs = 1.f / g_sumexp[tg];
    const float gt = g_gate[tg];
    const float ta = g_t_ad[(size_t)tg * H + hh];
    out_adapted[(size_t)tg * H + hh] = ta * (1.f - gt) + s * rs * gt;
}

// ---------------- launch ----------------
extern "C" void kernel_launch(void* const* d_in, const int* in_sizes, int n_in,
                              void* d_out, int out_size)
{
    (void)in_sizes; (void)n_in; (void)out_size;
    const float* src   = (const float*)d_in[0];
    const float* tgt   = (const float*)d_in[1];
    const float* sW1   = (const float*)d_in[2];
    const float* sb1   = (const float*)d_in[3];
    const float* sg    = (const float*)d_in[4];
    const float* sbeta = (const float*)d_in[5];
    const float* sW2   = (const float*)d_in[6];
    const float* sb2   = (const float*)d_in[7];
    const float* tW1   = (const float*)d_in[8];
    const float* tb1   = (const float*)d_in[9];
    const float* tg    = (const float*)d_in[10];
    const float* tbeta = (const float*)d_in[11];
    const float* tW2   = (const float*)d_in[12];
    const float* tb2   = (const float*)d_in[13];
    const float* cW    = (const float*)d_in[14];
    const float* cb    = (const float*)d_in[15];
    const float* cg    = (const float*)d_in[16];
    const float* cbeta = (const float*)d_in[17];
    const float* simW  = (const float*)d_in[18];
    const float* simb  = (const float*)d_in[19];

    float* out_adapted = (float*)d_out;                      // (B,T,H)
    float* out_scores  = out_adapted + (size_t)BB * TT * H;  // (B,T,S)

    adapter_kernel<DS, false><<<BB * SS / 4, 256>>>(src, sW1, sb1, sg, sbeta, sW2, sb2,
                                                    cW + H * H, nullptr);
    adapter_kernel<DT, true><<<BB * TT / 4, 256>>>(tgt, tW1, tb1, tg, tbeta, tW2, tb2,
                                                   cW, cb);
    score_kernel<<<(BB * TT) / TILE_T, 256>>>(cg, cbeta, simW, simb, out_scores);
    transfer_kernel<<<(BB * TT) / TTG, 512>>>(out_scores, out_adapted);
}

// round 6
// speedup vs baseline: 1.2346x; 1.2346x over previous
#include <cuda_runtime.h>
#include <math.h>

#define BB 2
#define SS 1024
#define TT 1024
#define DS 128
#define DT 64
#define H 64
#define LN_EPS 1e-5f

#define TILE_T 8
#define CH 32
#define USTRIDE 68   // floats; 272B row stride, 16B-aligned, conflict-free 16B reads
#define TTG 8        // t-rows per transfer block

typedef unsigned long long ull;

__device__ __forceinline__ ull fma2(ull a, ull b, ull c) {
    ull d; asm("fma.rn.f32x2 %0,%1,%2,%3;" : "=l"(d) : "l"(a), "l"(b), "l"(c)); return d;
}
__device__ __forceinline__ ull add2(ull a, ull b) {
    ull d; asm("add.rn.f32x2 %0,%1,%2;" : "=l"(d) : "l"(a), "l"(b)); return d;
}
__device__ __forceinline__ ull pack2(float lo, float hi) {
    ull d; asm("mov.b64 %0,{%1,%2};" : "=l"(d) : "f"(lo), "f"(hi)); return d;
}
__device__ __forceinline__ float2 unpack2(ull v) {
    float2 r; asm("mov.b64 {%0,%1},%2;" : "=f"(r.x), "=f"(r.y) : "l"(v)); return r;
}
__device__ __forceinline__ void cp16(void* smem_dst, const void* gsrc) {
    unsigned sa = (unsigned)__cvta_generic_to_shared(smem_dst);
    asm volatile("cp.async.cg.shared.global [%0], [%1], 16;" :: "r"(sa), "l"(gsrc));
}

// ---------------- scratch ----------------
__device__ float g_s_ad[BB * SS * H];
__device__ float g_u[BB * SS * H];
__device__ float g_t_ad[BB * TT * H];
__device__ float g_a[BB * TT * H];
__device__ float g_sum_u[BB * SS];
__device__ float g_su2[BB * SS];
__device__ float g_sum_a[BB * TT];
__device__ float g_sa2[BB * TT];
__device__ float g_gate[BB * TT];
__device__ float g_sumexp[BB * TT];

// constants for score kernel, 16B-aligned so pass-2 can use LDC.128
__constant__ __align__(16) float c_cg[H];
__constant__ __align__(16) float c_cb[H];
__constant__ __align__(16) float c_w[H];
__constant__ float c_simb[1];

// ---------------- adapter ----------------
template <int DIN, bool IS_TARGET>
__global__ __launch_bounds__(256)
void adapter_kernel(const float* __restrict__ X,
                    const float* __restrict__ W1, const float* __restrict__ b1,
                    const float* __restrict__ g,  const float* __restrict__ beta,
                    const float* __restrict__ W2, const float* __restrict__ b2,
                    const float* __restrict__ cWpart, const float* __restrict__ cb)
{
    __shared__ float sh_x[4][DIN];
    __shared__ float sh_r[4][H];
    __shared__ float sh_ad[4][H];
    __shared__ float sh_red[4][4];

    const int gid = threadIdx.x >> 6;
    const int j = threadIdx.x & 63;
    const int wid = j >> 5;
    const int row = blockIdx.x * 4 + gid;

    const float4* xrow4 = (const float4*)(X + (size_t)row * DIN);
    if (j < DIN / 4) ((float4*)sh_x[gid])[j] = xrow4[j];
    __syncthreads();

    const float* sx = sh_x[gid];
    float h0 = 0.f, h1 = 0.f, h2 = 0.f, h3 = 0.f;
#pragma unroll
    for (int k = 0; k < DIN; k += 4) {
        h0 = fmaf(sx[k],     W1[(k)     * H + j], h0);
        h1 = fmaf(sx[k + 1], W1[(k + 1) * H + j], h1);
        h2 = fmaf(sx[k + 2], W1[(k + 2) * H + j], h2);
        h3 = fmaf(sx[k + 3], W1[(k + 3) * H + j], h3);
    }
    float h = ((h0 + h1) + (h2 + h3)) + b1[j];

    float s1 = h, s2 = h * h;
#pragma unroll
    for (int o = 16; o; o >>= 1) {
        s1 += __shfl_xor_sync(~0u, s1, o);
        s2 += __shfl_xor_sync(~0u, s2, o);
    }
    if ((j & 31) == 0) { sh_red[gid][wid] = s1; sh_red[gid][2 + wid] = s2; }
    __syncthreads();
    const float m   = (sh_red[gid][0] + sh_red[gid][1]) * (1.f / H);
    const float e2  = (sh_red[gid][2] + sh_red[gid][3]) * (1.f / H);
    const float inv = rsqrtf(e2 - m * m + LN_EPS);
    float r = (h - m) * inv * g[j] + beta[j];
    r = fmaxf(r, 0.f);
    __syncthreads();
    sh_r[gid][j] = r;
    __syncthreads();

    const float* sr = sh_r[gid];
    float a0 = 0.f, a1 = 0.f, a2v = 0.f, a3 = 0.f;
#pragma unroll
    for (int k = 0; k < H; k += 4) {
        a0  = fmaf(sr[k],     W2[(k)     * H + j], a0);
        a1  = fmaf(sr[k + 1], W2[(k + 1) * H + j], a1);
        a2v = fmaf(sr[k + 2], W2[(k + 2) * H + j], a2v);
        a3  = fmaf(sr[k + 3], W2[(k + 3) * H + j], a3);
    }
    float ad = ((a0 + a1) + (a2v + a3)) + b2[j];

    if (IS_TARGET) {
        g_t_ad[(size_t)row * H + j] = ad;
        float s = ad;
#pragma unroll
        for (int o = 16; o; o >>= 1) s += __shfl_xor_sync(~0u, s, o);
        if ((j & 31) == 0) sh_red[gid][wid] = s;
    } else {
        g_s_ad[(size_t)row * H + j] = ad;
    }
    sh_ad[gid][j] = ad;
    __syncthreads();

    if (IS_TARGET && j == 0) {
        float mt = (sh_red[gid][0] + sh_red[gid][1]) * (1.f / H);
        g_gate[row] = 1.f / (1.f + __expf(-mt));
    }

    const float* sa = sh_ad[gid];
    float p0 = IS_TARGET ? cb[j] : 0.f, p1k = 0.f, p2k = 0.f, p3k = 0.f;
#pragma unroll
    for (int k = 0; k < H; k += 4) {
        p0  = fmaf(sa[k],     cWpart[(k)     * H + j], p0);
        p1k = fmaf(sa[k + 1], cWpart[(k + 1) * H + j], p1k);
        p2k = fmaf(sa[k + 2], cWpart[(k + 2) * H + j], p2k);
        p3k = fmaf(sa[k + 3], cWpart[(k + 3) * H + j], p3k);
    }
    float p = ((p0 + p1k) + (p2k + p3k));

    if (IS_TARGET) g_a[(size_t)row * H + j] = p;
    else           g_u[(size_t)row * H + j] = p;

    float q1 = p, q2 = p * p;
#pragma unroll
    for (int o = 16; o; o >>= 1) {
        q1 += __shfl_xor_sync(~0u, q1, o);
        q2 += __shfl_xor_sync(~0u, q2, o);
    }
    __syncthreads();
    if ((j & 31) == 0) { sh_red[gid][wid] = q1; sh_red[gid][2 + wid] = q2; }
    __syncthreads();
    if (j == 0) {
        if (IS_TARGET) { g_sum_a[row] = sh_red[gid][0] + sh_red[gid][1]; g_sa2[row] = sh_red[gid][2] + sh_red[gid][3]; }
        else           { g_sum_u[row] = sh_red[gid][0] + sh_red[gid][1]; g_su2[row] = sh_red[gid][2] + sh_red[gid][3]; }
    }
}

// ---------------- score kernel: u in regs, a in smem, constants via LDC.128 ----
__global__ __launch_bounds__(256, 2)
void score_kernel(float* __restrict__ out_scores)
{
    __shared__ __align__(16) float u_sh[2][CH * USTRIDE];
    __shared__ __align__(16) float a_sh[TILE_T][H];

    const int tid = threadIdx.x;
    const int lane = tid & 31;
    const int w = tid >> 5;
    const int tglob = blockIdx.x * TILE_T + w;
    const int b = tglob >> 10;
    const int srow0 = b << 10;

    // stage this warp's a row to shared (warp-uniform -> broadcast reads later)
    ((float2*)a_sh[w])[lane] = ((const float2*)(g_a + (size_t)tglob * H))[lane];

    const float suma = g_sum_a[tglob];
    const float sqa  = g_sa2[tglob];
    const float simb0 = c_simb[0];

    // prologue: stage chunk 0
    {
        const float4* src = (const float4*)(g_u + (size_t)srow0 * H);
#pragma unroll
        for (int rep = 0; rep < 2; rep++) {
            int f = tid + rep * 256;
            int r = f >> 4, q = f & 15;
            cp16(&u_sh[0][r * USTRIDE + q * 4], src + f);
        }
        asm volatile("cp.async.commit_group;");
    }

    float sumexp = 0.f;
    float* srow_out = out_scores + (size_t)tglob * SS;
    __syncthreads();   // a_sh visible

    for (int c = 0; c < SS / CH; c++) {
        if (c < SS / CH - 1) {
            const float4* src = (const float4*)(g_u + (size_t)(srow0 + (c + 1) * CH) * H);
            float* dst = u_sh[(c + 1) & 1];
#pragma unroll
            for (int rep = 0; rep < 2; rep++) {
                int f = tid + rep * 256;
                int r = f >> 4, q = f & 15;
                cp16(&dst[r * USTRIDE + q * 4], src + f);
            }
            asm volatile("cp.async.commit_group;");
            asm volatile("cp.async.wait_group 1;");
        } else {
            asm volatile("cp.async.wait_group 0;");
        }
        __syncthreads();

        // load u row for this lane's s ONCE into registers
        const ulonglong2* up2 = (const ulonglong2*)&u_sh[c & 1][lane * USTRIDE];
        ull u2[H / 2];
#pragma unroll
        for (int i = 0; i < H / 4; i++) {
            ulonglong2 v = up2[i];
            u2[2 * i] = v.x; u2[2 * i + 1] = v.y;
        }

        const int sidx = srow0 + c * CH + lane;
        const float su  = g_sum_u[sidx];
        const float squ = g_su2[sidx];

        const ulonglong2* ap2 = (const ulonglong2*)a_sh[w];

        // pass 1: dot(a,u), a via broadcast LDS
        ull d0 = 0ull, d1 = 0ull, d2 = 0ull, d3 = 0ull;
#pragma unroll
        for (int i = 0; i < H / 4; i += 2) {
            ulonglong2 aa = ap2[i];
            ulonglong2 ab = ap2[i + 1];
            d0 = fma2(aa.x, u2[2 * i],     d0);
            d1 = fma2(aa.y, u2[2 * i + 1], d1);
            d2 = fma2(ab.x, u2[2 * i + 2], d2);
            d3 = fma2(ab.y, u2[2 * i + 3], d3);
        }
        float2 f0 = unpack2(d0), f1 = unpack2(d1), f2 = unpack2(d2), f3 = unpack2(d3);
        const float dot = ((f0.x + f0.y) + (f1.x + f1.y)) + ((f2.x + f2.y) + (f3.x + f3.y));

        const float m   = (suma + su) * (1.f / H);
        const float e2  = (sqa + 2.f * dot + squ) * (1.f / H);
        const float inv = rsqrtf(e2 - m * m + LN_EPS);
        const float nm  = -m * inv;
        const ull inv2 = pack2(inv, inv);
        const ull nm2  = pack2(nm, nm);

        // pass 2: packed math; constants as 16B LDC.128 (3 per i instead of 6 LDC.64)
        ull acca = 0ull, accb = 0ull;
#pragma unroll
        for (int i = 0; i < H / 4; i++) {
            ulonglong2 aa  = ap2[i];
            ulonglong2 kcg = *(const ulonglong2*)&c_cg[4 * i];
            ulonglong2 kcb = *(const ulonglong2*)&c_cb[4 * i];
            ulonglong2 kw  = *(const ulonglong2*)&c_w[4 * i];
            ull p0 = add2(aa.x, u2[2 * i]);
            ull p1 = add2(aa.y, u2[2 * i + 1]);
            ull z0 = fma2(p0, inv2, nm2);
            ull z1 = fma2(p1, inv2, nm2);
            ull y0 = fma2(z0, kcg.x, kcb.x);
            ull y1 = fma2(z1, kcg.y, kcb.y);
            float2 ya = unpack2(y0), yb = unpack2(y1);
            ya.x = fmaxf(ya.x, 0.f); ya.y = fmaxf(ya.y, 0.f);
            yb.x = fmaxf(yb.x, 0.f); yb.y = fmaxf(yb.y, 0.f);
            acca = fma2(pack2(ya.x, ya.y), kw.x, acca);
            accb = fma2(pack2(yb.x, yb.y), kw.y, accb);
        }
        float2 sa2 = unpack2(acca), sb2 = unpack2(accb);
        const float acc = (sa2.x + sa2.y) + (sb2.x + sb2.y);
        const float score = 1.f / (1.f + __expf(-(acc + simb0)));
        srow_out[c * CH + lane] = score;
        sumexp += __expf(score);

        __syncthreads();   // reads of this buffer done before re-stage
    }

#pragma unroll
    for (int o = 16; o; o >>= 1) sumexp += __shfl_xor_sync(~0u, sumexp, o);
    if (lane == 0) g_sumexp[tglob] = sumexp;
}

// ---------------- transfer: 512 threads / 16 warps, warp covers 64 s, TTG=8 t-rows ----
__global__ __launch_bounds__(512)
void transfer_kernel(const float* __restrict__ scores, float* __restrict__ out_adapted)
{
    __shared__ __align__(16) ull e2_sh[16][32 * TTG];   // 32 KB duplicated-exp per warp
    __shared__ __align__(16) float red[16 * TTG * H];   // 32 KB per-warp partials

    const int tid = threadIdx.x;
    const int w = tid >> 5, lane = tid & 31;
    const int tbase = blockIdx.x * TTG;
    const int b = tbase >> 10;
    const int srow0 = b << 10;

    ull acc2[TTG];
#pragma unroll
    for (int t = 0; t < TTG; t++) acc2[t] = 0ull;

    for (int c = 0; c < 2; c++) {
        const int sloc0 = w * 64 + c * 32;

#pragma unroll
        for (int t = 0; t < TTG; t++) {
            float e = __expf(scores[(size_t)(tbase + t) * SS + sloc0 + lane]);
            e2_sh[w][lane * TTG + t] = pack2(e, e);
        }
        __syncwarp();

#pragma unroll 4
        for (int j = 0; j < 32; j += 8) {
            // batch 8 independent s_ad loads (MLP=8)
            ull v[8];
#pragma unroll
            for (int k = 0; k < 8; k++)
                v[k] = *(const ull*)(g_s_ad + (size_t)(srow0 + sloc0 + j + k) * H + 2 * lane);
#pragma unroll
            for (int k = 0; k < 8; k++) {
                const ulonglong2* ep = (const ulonglong2*)&e2_sh[w][(j + k) * TTG];
                ulonglong2 e01 = ep[0], e23 = ep[1], e45 = ep[2], e67 = ep[3];
                acc2[0] = fma2(v[k], e01.x, acc2[0]);
                acc2[1] = fma2(v[k], e01.y, acc2[1]);
                acc2[2] = fma2(v[k], e23.x, acc2[2]);
                acc2[3] = fma2(v[k], e23.y, acc2[3]);
                acc2[4] = fma2(v[k], e45.x, acc2[4]);
                acc2[5] = fma2(v[k], e45.y, acc2[5]);
                acc2[6] = fma2(v[k], e67.x, acc2[6]);
                acc2[7] = fma2(v[k], e67.y, acc2[7]);
            }
        }
        __syncwarp();
    }

#pragma unroll
    for (int t = 0; t < TTG; t++)
        *(ull*)&red[(w * TTG + t) * H + 2 * lane] = acc2[t];
    __syncthreads();

    const int t = tid >> 6;
    const int hh = tid & 63;
    float s = 0.f;
#pragma unroll
    for (int ww = 0; ww < 16; ww++) s += red[(ww * TTG + t) * H + hh];

    const int tg = tbase + t;
    const float rs = 1.f / g_sumexp[tg];
    const float gt = g_gate[tg];
    const float ta = g_t_ad[(size_t)tg * H + hh];
    out_adapted[(size_t)tg * H + hh] = ta * (1.f - gt) + s * rs * gt;
}

// ---------------- launch ----------------
extern "C" void kernel_launch(void* const* d_in, const int* in_sizes, int n_in,
                              void* d_out, int out_size)
{
    (void)in_sizes; (void)n_in; (void)out_size;
    const float* src   = (const float*)d_in[0];
    const float* tgt   = (const float*)d_in[1];
    const float* sW1   = (const float*)d_in[2];
    const float* sb1   = (const float*)d_in[3];
    const float* sg    = (const float*)d_in[4];
    const float* sbeta = (const float*)d_in[5];
    const float* sW2   = (const float*)d_in[6];
    const float* sb2   = (const float*)d_in[7];
    const float* tW1   = (const float*)d_in[8];
    const float* tb1   = (const float*)d_in[9];
    const float* tg    = (const float*)d_in[10];
    const float* tbeta = (const float*)d_in[11];
    const float* tW2   = (const float*)d_in[12];
    const float* tb2   = (const float*)d_in[13];
    const float* cW    = (const float*)d_in[14];
    const float* cb    = (const float*)d_in[15];
    const float* cg    = (const float*)d_in[16];
    const float* cbeta = (const float*)d_in[17];
    const float* simW  = (const float*)d_in[18];
    const float* simb  = (const float*)d_in[19];

    float* out_adapted = (float*)d_out;                      // (B,T,H)
    float* out_scores  = out_adapted + (size_t)BB * TT * H;  // (B,T,S)

    cudaMemcpyToSymbolAsync(c_cg,   cg,    H * sizeof(float), 0, cudaMemcpyDeviceToDevice, 0);
    cudaMemcpyToSymbolAsync(c_cb,   cbeta, H * sizeof(float), 0, cudaMemcpyDeviceToDevice, 0);
    cudaMemcpyToSymbolAsync(c_w,    simW,  H * sizeof(float), 0, cudaMemcpyDeviceToDevice, 0);
    cudaMemcpyToSymbolAsync(c_simb, simb,  sizeof(float),     0, cudaMemcpyDeviceToDevice, 0);

    adapter_kernel<DS, false><<<BB * SS / 4, 256>>>(src, sW1, sb1, sg, sbeta, sW2, sb2,
                                                    cW + H * H, nullptr);
    adapter_kernel<DT, true><<<BB * TT / 4, 256>>>(tgt, tW1, tb1, tg, tbeta, tW2, tb2,
                                                   cW, cb);
    score_kernel<<<(BB * TT) / TILE_T, 256>>>(out_scores);
    transfer_kernel<<<(BB * TT) / TTG, 512>>>(out_scores, out_adapted);
}